// round 1
// baseline (speedup 1.0000x reference)
#include <cuda_runtime.h>
#include <cuda_bf16.h>
#include <math.h>

// Problem constants
#define T_TOKENS 16384
#define H_DIM    2048
#define N_EXP    64
#define TOP_K    8

// ---------------------------------------------------------------------------
// Kernel 1: fp32 SGEMM  logits[T,64] = hidden[T,2048] @ weight[64,2048]^T
// Block tile: 64 tokens x 64 experts, BK=32. 256 threads, 4x4 microtile each.
// Smem tiles stored k-major ([k][m]) for conflict-free float4 compute reads.
// ---------------------------------------------------------------------------
__global__ __launch_bounds__(256) void router_gemm_kernel(
    const float* __restrict__ A,   // [T, H] hidden
    const float* __restrict__ W,   // [E, H] weight
    float* __restrict__ out)       // [T, E] logits
{
    __shared__ float As[32][64];
    __shared__ float Bs[32][64];

    const int tid = threadIdx.x;
    const int tx  = tid & 15;        // expert dim, 0..15
    const int ty  = tid >> 4;        // token dim,  0..15
    const int blockRow = blockIdx.x * 64;

    float acc[4][4];
#pragma unroll
    for (int i = 0; i < 4; i++)
#pragma unroll
        for (int j = 0; j < 4; j++) acc[i][j] = 0.0f;

    for (int k0 = 0; k0 < H_DIM; k0 += 32) {
        // Cooperative load: 64 rows x 32 k for both tiles (512 float4 each).
#pragma unroll
        for (int v = 0; v < 2; v++) {
            int vecId = tid + v * 256;        // 0..511
            int row   = vecId >> 3;           // 0..63
            int c4    = (vecId & 7) << 2;     // 0,4,...,28

            float4 a = *(const float4*)&A[(size_t)(blockRow + row) * H_DIM + k0 + c4];
            As[c4 + 0][row] = a.x;
            As[c4 + 1][row] = a.y;
            As[c4 + 2][row] = a.z;
            As[c4 + 3][row] = a.w;

            float4 b = *(const float4*)&W[(size_t)row * H_DIM + k0 + c4];
            Bs[c4 + 0][row] = b.x;
            Bs[c4 + 1][row] = b.y;
            Bs[c4 + 2][row] = b.z;
            Bs[c4 + 3][row] = b.w;
        }
        __syncthreads();

#pragma unroll
        for (int k = 0; k < 32; k++) {
            float4 av = *(const float4*)&As[k][ty << 2];
            float4 bv = *(const float4*)&Bs[k][tx << 2];
            float af[4] = {av.x, av.y, av.z, av.w};
            float bf[4] = {bv.x, bv.y, bv.z, bv.w};
#pragma unroll
            for (int i = 0; i < 4; i++)
#pragma unroll
                for (int j = 0; j < 4; j++)
                    acc[i][j] = fmaf(af[i], bf[j], acc[i][j]);
        }
        __syncthreads();
    }

#pragma unroll
    for (int i = 0; i < 4; i++) {
        int row = blockRow + (ty << 2) + i;
        float4 o = make_float4(acc[i][0], acc[i][1], acc[i][2], acc[i][3]);
        *(float4*)&out[(size_t)row * N_EXP + (tx << 2)] = o;
    }
}

// ---------------------------------------------------------------------------
// Kernel 2: per-token top-8 + renormalized softmax values.
// One warp per token. Lane l holds logits[l] and logits[l+32].
// Iterative warp argmax (tie -> lower index, matching jax.lax.top_k).
// Renormalized value_i = exp(l_i - m) / sum_top8 exp(l_j - m)
// (full softmax denominator cancels).
// ---------------------------------------------------------------------------
__global__ __launch_bounds__(256) void router_topk_kernel(
    const float* __restrict__ logits,  // [T, 64]
    float* __restrict__ vals,          // [T, 8]
    float* __restrict__ inds)          // [T, 8] (indices stored as float)
{
    const int warp = (blockIdx.x * blockDim.x + threadIdx.x) >> 5;
    const int lane = threadIdx.x & 31;
    if (warp >= T_TOKENS) return;

    const float* row = logits + (size_t)warp * N_EXP;
    float v0 = row[lane];
    float v1 = row[lane + 32];

    float top_v[TOP_K];
    int   top_i[TOP_K];

#pragma unroll
    for (int it = 0; it < TOP_K; it++) {
        // Local candidate: prefer lower index on ties (lane < lane+32 always).
        float bv; int bi;
        if (v1 > v0) { bv = v1; bi = lane + 32; }
        else         { bv = v0; bi = lane; }
        // Warp all-reduce argmax, tie -> lower index (associative+commutative).
#pragma unroll
        for (int off = 16; off; off >>= 1) {
            float ov = __shfl_xor_sync(0xffffffffu, bv, off);
            int   oi = __shfl_xor_sync(0xffffffffu, bi, off);
            if (ov > bv || (ov == bv && oi < bi)) { bv = ov; bi = oi; }
        }
        top_v[it] = bv;
        top_i[it] = bi;
        if (bi == lane)      v0 = -INFINITY;
        if (bi == lane + 32) v1 = -INFINITY;
    }

    const float m = top_v[0];
    float s = 0.0f;
#pragma unroll
    for (int i = 0; i < TOP_K; i++) s += expf(top_v[i] - m);

    if (lane < TOP_K) {
        vals[(size_t)warp * TOP_K + lane] = expf(top_v[lane] - m) / s;
        inds[(size_t)warp * TOP_K + lane] = (float)top_i[lane];
    }
}

// ---------------------------------------------------------------------------
// Launch
// ---------------------------------------------------------------------------
extern "C" void kernel_launch(void* const* d_in, const int* in_sizes, int n_in,
                              void* d_out, int out_size)
{
    const float* hidden = (const float*)d_in[0];   // [16384, 2048]
    const float* weight = (const float*)d_in[1];   // [64, 2048]
    float* out = (float*)d_out;

    float* logits = out;                                        // 16384*64
    float* vals   = out + (size_t)T_TOKENS * N_EXP;             // 16384*8
    float* inds   = vals + (size_t)T_TOKENS * TOP_K;            // 16384*8

    router_gemm_kernel<<<T_TOKENS / 64, 256>>>(hidden, weight, logits);
    // 8 warps per block -> 8 tokens per block
    router_topk_kernel<<<T_TOKENS / 8, 256>>>(logits, vals, inds);
}